// round 4
// baseline (speedup 1.0000x reference)
#include <cuda_runtime.h>

#define GH 96
#define GW 96
#define HW (GH*GW)
#define BSZ 8
#define LN 16
#define PN 16
#define NCELL (BSZ*GH*GW)     /* 73728 */
#define TPB 256
#define CPB (TPB/4)           /* 64 cells per block, 4 threads per cell */
#define NBLK (NCELL/CPB)      /* 1152 */

__device__ float g_partials[NBLK];
__device__ unsigned int g_ticket;   // zero-init; last block resets it

__device__ __forceinline__ float asqrt(float x) {
    float r;
    asm("sqrt.approx.f32 %0, %1;" : "=f"(r) : "f"(x));
    return r;
}

__global__ __launch_bounds__(TPB, 4)
void yolino_main(const float* __restrict__ target, const float* __restrict__ pred,
                 float* __restrict__ out)
{
    const int tid  = threadIdx.x;
    const int lane = tid & 31;
    const int g    = tid & 3;                 // line-group: handles lines [4g, 4g+4)
    const int n    = blockIdx.x * CPB + (tid >> 2);   // grid cell

    const int w  = n % GW;
    const int t1 = n / GW;
    const int h  = t1 % GH;
    const int b  = t1 / GH;

    // This thread's 4 target lines = channels [g*16, g*16+16)
    const float* tb = target + (size_t)b * 64 * HW + (size_t)(g * 16) * HW
                             + (size_t)h * GW + w;
    const float* pb = pred   + (size_t)b * 96 * HW + (size_t)h * GW + w;

    float tlv[4][4];
    #pragma unroll
    for (int l = 0; l < 4; ++l) {
        #pragma unroll
        for (int j = 0; j < 4; ++j)
            tlv[l][j] = tb[(size_t)(l * 4 + j) * HW];
    }

    // Valid-line mask for this thread's 4 lines
    unsigned tmask = 0;
    #pragma unroll
    for (int l = 0; l < 4; ++l) {
        float s = (tlv[l][0] + tlv[l][1]) + (tlv[l][2] + tlv[l][3]);
        if (s > 0.f) tmask |= (1u << l);
    }

    // Sub-warp group mask: the 4 lanes sharing this cell (consecutive lanes)
    const unsigned gmask = 0xFu << (lane & 28);

    float loss = 0.f;

    // Prefetch predictor 0's six channels.
    float q0 = pb[0], q1 = pb[HW], q2 = pb[2 * HW],
          q3 = pb[3 * HW], q4 = pb[4 * HW], q5 = pb[5 * HW];

    #pragma unroll 1
    for (int p = 0; p < PN; ++p) {
        const float c0 = q0, c1 = q1, c2 = q2, c3 = q3, c4 = q4, c5 = q5;

        if (p + 1 < PN) {
            const float* nb = pb + (size_t)((p + 1) * 6) * HW;
            q0 = nb[0];      q1 = nb[HW];     q2 = nb[2 * HW];
            q3 = nb[3 * HW]; q4 = nb[4 * HW]; q5 = nb[5 * HW];
        }

        float d[4];
        float m = 3.4e38f;
        #pragma unroll
        for (int l = 0; l < 4; ++l) {
            float dx1 = tlv[l][0] - c0, dy1 = tlv[l][1] - c1;
            float dx2 = tlv[l][2] - c2, dy2 = tlv[l][3] - c3;
            float s1 = fmaf(dx1, dx1, dy1 * dy1);
            float s2 = fmaf(dx2, dx2, dy2 * dy2);
            float dd = asqrt(s1) + asqrt(s2);
            d[l] = dd;
            m = fminf(m, dd);
        }

        // Combine min over the cell's 16 lines (4 partner lanes)
        m = fminf(m, __shfl_xor_sync(0xffffffffu, m, 1));
        m = fminf(m, __shfl_xor_sync(0xffffffffu, m, 2));

        const float thr = (m < 2.f) ? m : -1.f;

        float cnt  = 0.f;
        float dsum = 0.f;
        #pragma unroll
        for (int l = 0; l < 4; ++l) {
            bool sel = (d[l] == thr) && ((tmask >> l) & 1u);
            if (sel) { dsum += d[l]; cnt += 1.f; }
        }
        loss += dsum;

        // ik_mask = any selected line among all 16 (across the 4 partner lanes)
        bool anyk = __any_sync(gmask, cnt > 0.f);

        // Confidence term: added once per cell (group 0 only)
        if (g == 0) {
            float sig = 1.f / (1.f + __expf(-c4));
            float e   = anyk ? (sig - 1.f) : sig;
            loss = fmaf(e, e, loss);
        }

        // Class term: (1 - cls_hard)^2 over this thread's selected lines.
        // cls_hard = sigmoid(c5) > 0.5  <=>  c5 > 0
        if (!(c5 > 0.f)) loss += cnt;
    }

    // ---- block reduction (deterministic) ----
    #pragma unroll
    for (int o = 16; o > 0; o >>= 1)
        loss += __shfl_xor_sync(0xffffffffu, loss, o);

    __shared__ float sw[TPB / 32];
    __shared__ bool  s_last;
    const int wid = tid >> 5;
    if (lane == 0) sw[wid] = loss;
    __syncthreads();
    if (wid == 0) {
        float v = (lane < TPB / 32) ? sw[lane] : 0.f;
        #pragma unroll
        for (int o = 4; o > 0; o >>= 1)
            v += __shfl_xor_sync(0xffffffffu, v, o);
        if (lane == 0) {
            g_partials[blockIdx.x] = v;
            __threadfence();
            unsigned t = atomicAdd(&g_ticket, 1u);
            s_last = (t == NBLK - 1);
        }
    }
    __syncthreads();

    // ---- last block folds all partials into the output ----
    if (s_last) {
        __threadfence();  // acquire: make all g_partials visible
        const int t = tid;
        float v = 0.f;
        #pragma unroll
        for (int i = 0; i < NBLK / TPB; ++i)      // 1152/256 = 4.5 -> handled below
            v += g_partials[t + i * TPB];
        if (t + (NBLK / TPB) * TPB < NBLK)
            v += g_partials[t + (NBLK / TPB) * TPB];
        __shared__ float s[TPB];
        s[t] = v;
        __syncthreads();
        #pragma unroll
        for (int o = TPB / 2; o > 0; o >>= 1) {
            if (t < o) s[t] += s[t + o];
            __syncthreads();
        }
        if (t == 0) {
            out[0] = s[0] * (1.0f / BSZ);
            g_ticket = 0;   // reset for the next (graph-replayed) launch
        }
    }
}

extern "C" void kernel_launch(void* const* d_in, const int* in_sizes, int n_in,
                              void* d_out, int out_size)
{
    const float* target = (const float*)d_in[0];
    const float* pred   = (const float*)d_in[1];
    float* out = (float*)d_out;

    yolino_main<<<NBLK, TPB>>>(target, pred, out);
}

// round 5
// speedup vs baseline: 1.4089x; 1.4089x over previous
#include <cuda_runtime.h>

#define GH 96
#define GW 96
#define HW (GH*GW)
#define BSZ 8
#define LN 16
#define PN 16
#define NCELL (BSZ*GH*GW)   /* 73728 */
#define TPB 128
#define NBLK (NCELL/TPB)    /* 576 */

__device__ float g_partials[NBLK];
__device__ unsigned int g_ticket;   // zero-init; last block resets it

__device__ __forceinline__ float asqrt(float x) {
    float r;
    asm("sqrt.approx.f32 %0, %1;" : "=f"(r) : "f"(x));
    return r;
}

__global__ __launch_bounds__(TPB, 5)
void yolino_main(const float* __restrict__ target, const float* __restrict__ pred,
                 float* __restrict__ out)
{
    const int n = blockIdx.x * TPB + threadIdx.x;   // n in [0, NCELL)
    const int w  = n % GW;
    const int t1 = n / GW;
    const int h  = t1 % GH;
    const int b  = t1 / GH;

    // 32-bit offsets throughout (max offset ~7.1M < 2^31)
    const float* tb = target + b * (64 * HW) + h * GW + w;
    const float* pb = pred   + b * (96 * HW) + h * GW + w;

    // Load all 16 target lines (4 coords each) — coalesced across the warp.
    float tlv[LN][4];
    #pragma unroll
    for (int l = 0; l < LN; ++l) {
        #pragma unroll
        for (int j = 0; j < 4; ++j)
            tlv[l][j] = tb[(l * 4 + j) * HW];
    }

    // Valid-line mask: sum of the 4 coords > 0
    unsigned tmask = 0;
    #pragma unroll
    for (int l = 0; l < LN; ++l) {
        float s = (tlv[l][0] + tlv[l][1]) + (tlv[l][2] + tlv[l][3]);
        if (s > 0.f) tmask |= (1u << l);
    }

    float loss = 0.f;

    // Prefetch predictor 0's six channels.
    float q0 = pb[0], q1 = pb[HW], q2 = pb[2 * HW],
          q3 = pb[3 * HW], q4 = pb[4 * HW], q5 = pb[5 * HW];

    #pragma unroll 1
    for (int p = 0; p < PN; ++p) {
        const float c0 = q0, c1 = q1, c2 = q2, c3 = q3, c4 = q4, c5 = q5;

        // Prefetch next predictor while we crunch this one.
        if (p + 1 < PN) {
            const float* nb = pb + (p + 1) * (6 * HW);
            q0 = nb[0];      q1 = nb[HW];     q2 = nb[2 * HW];
            q3 = nb[3 * HW]; q4 = nb[4 * HW]; q5 = nb[5 * HW];
        }

        // Tie-tracking argmin scan over the 16 lines.
        // After the loop: m = min dist, am = bitmask of lines achieving m.
        float m = 3.4e38f;
        unsigned am = 0;
        #pragma unroll
        for (int l = 0; l < LN; ++l) {
            float dx1 = tlv[l][0] - c0, dy1 = tlv[l][1] - c1;
            float dx2 = tlv[l][2] - c2, dy2 = tlv[l][3] - c3;
            float s1 = fmaf(dx1, dx1, dy1 * dy1);
            float s2 = fmaf(dx2, dx2, dy2 * dy2);
            float dd = asqrt(s1) + asqrt(s2);
            if (dd < m)       { m = dd; am = (1u << l); }
            else if (dd == m) { am |= (1u << l); }
        }

        // thr = (m<2) ? m : -1.  dist==thr selects exactly the tie set when m<2,
        // and nothing when thr==-1 (distances are >= 0).
        float cnt = 0.f;
        if (m < 2.f) cnt = (float)__popc(am & tmask);

        // dist term: every selected entry has dist == m
        loss = fmaf(m, cnt, loss);

        // Confidence term: (sig-1)^2 if any match else sig^2
        float sig = 1.f / (1.f + __expf(-c4));
        float e   = (cnt > 0.f) ? (sig - 1.f) : sig;
        loss = fmaf(e, e, loss);

        // Class term: (1 - cls_hard)^2 per selected line; cls_hard=1 <=> c5>0
        if (!(c5 > 0.f)) loss += cnt;
    }

    // ---- block reduction (deterministic) ----
    #pragma unroll
    for (int o = 16; o > 0; o >>= 1)
        loss += __shfl_xor_sync(0xffffffffu, loss, o);

    __shared__ float sw[TPB / 32];
    __shared__ bool  s_last;
    const int lane = threadIdx.x & 31;
    const int wid  = threadIdx.x >> 5;
    if (lane == 0) sw[wid] = loss;
    __syncthreads();
    if (wid == 0) {
        float v = (lane < TPB / 32) ? sw[lane] : 0.f;
        #pragma unroll
        for (int o = 2; o > 0; o >>= 1)
            v += __shfl_xor_sync(0xffffffffu, v, o);
        if (lane == 0) {
            g_partials[blockIdx.x] = v;
            __threadfence();
            unsigned t = atomicAdd(&g_ticket, 1u);
            s_last = (t == NBLK - 1);
        }
    }
    __syncthreads();

    // ---- last block folds all partials into the output ----
    if (s_last) {
        __threadfence();  // acquire: make all g_partials visible
        const int t = threadIdx.x;
        float v = 0.f;
        for (int i = t; i < NBLK; i += TPB)   // fixed per-thread order: deterministic
            v += g_partials[i];
        __shared__ float s[TPB];
        s[t] = v;
        __syncthreads();
        #pragma unroll
        for (int o = TPB / 2; o > 0; o >>= 1) {
            if (t < o) s[t] += s[t + o];
            __syncthreads();
        }
        if (t == 0) {
            out[0] = s[0] * (1.0f / BSZ);
            g_ticket = 0;   // reset for the next (graph-replayed) launch
        }
    }
}

extern "C" void kernel_launch(void* const* d_in, const int* in_sizes, int n_in,
                              void* d_out, int out_size)
{
    const float* target = (const float*)d_in[0];
    const float* pred   = (const float*)d_in[1];
    float* out = (float*)d_out;

    yolino_main<<<NBLK, TPB>>>(target, pred, out);
}

// round 6
// speedup vs baseline: 1.6319x; 1.1583x over previous
#include <cuda_runtime.h>

#define GH 96
#define GW 96
#define HW (GH*GW)
#define BSZ 8
#define LN 16
#define PN 16
#define NCELL (BSZ*GH*GW)   /* 73728 */
#define TPB 128
#define NBLK (NCELL/TPB)    /* 576 */

__device__ float g_partials[NBLK];
__device__ unsigned int g_ticket;   // zero-init; last block resets it

__device__ __forceinline__ float asqrt(float x) {
    float r;
    asm("sqrt.approx.f32 %0, %1;" : "=f"(r) : "f"(x));
    return r;
}

__global__ __launch_bounds__(TPB, 4)
void yolino_main(const float* __restrict__ target, const float* __restrict__ pred,
                 float* __restrict__ out)
{
    const int n = blockIdx.x * TPB + threadIdx.x;   // n in [0, NCELL)
    const int w  = n % GW;
    const int t1 = n / GW;
    const int h  = t1 % GH;
    const int b  = t1 / GH;

    // 32-bit offsets (max ~7.1M elements < 2^31)
    const float* tb = target + b * (64 * HW) + h * GW + w;
    const float* pb = pred   + b * (96 * HW) + h * GW + w;

    // Load all 16 target lines (4 coords each) — coalesced across the warp.
    float tlv[LN][4];
    #pragma unroll
    for (int l = 0; l < LN; ++l) {
        #pragma unroll
        for (int j = 0; j < 4; ++j)
            tlv[l][j] = tb[(l * 4 + j) * HW];
    }

    // Valid-line mask: sum of the 4 coords > 0
    unsigned tmask = 0;
    #pragma unroll
    for (int l = 0; l < LN; ++l) {
        float s = (tlv[l][0] + tlv[l][1]) + (tlv[l][2] + tlv[l][3]);
        if (s > 0.f) tmask |= (1u << l);
    }

    float loss = 0.f;

    // Prefetch predictor 0's six channels.
    float q0 = pb[0], q1 = pb[HW], q2 = pb[2 * HW],
          q3 = pb[3 * HW], q4 = pb[4 * HW], q5 = pb[5 * HW];

    #pragma unroll 1
    for (int p = 0; p < PN; ++p) {
        const float c0 = q0, c1 = q1, c2 = q2, c3 = q3, c4 = q4, c5 = q5;

        // Prefetch next predictor while we crunch this one.
        if (p + 1 < PN) {
            const float* nb = pb + (p + 1) * (6 * HW);
            q0 = nb[0];      q1 = nb[HW];     q2 = nb[2 * HW];
            q3 = nb[3 * HW]; q4 = nb[4 * HW]; q5 = nb[5 * HW];
        }

        // Pass 1: 16 fully independent distance computations (max ILP).
        float d[LN];
        #pragma unroll
        for (int l = 0; l < LN; ++l) {
            float dx1 = tlv[l][0] - c0, dy1 = tlv[l][1] - c1;
            float dx2 = tlv[l][2] - c2, dy2 = tlv[l][3] - c3;
            float s1 = fmaf(dx1, dx1, dy1 * dy1);
            float s2 = fmaf(dx2, dx2, dy2 * dy2);
            d[l] = asqrt(s1) + asqrt(s2);
        }

        // Pass 2: tree min (depth 4, no serial chain).
        float mm[8];
        #pragma unroll
        for (int i = 0; i < 8; ++i) mm[i] = fminf(d[2 * i], d[2 * i + 1]);
        #pragma unroll
        for (int i = 0; i < 4; ++i) mm[i] = fminf(mm[i], mm[i + 4]);
        mm[0] = fminf(mm[0], mm[2]);
        mm[1] = fminf(mm[1], mm[3]);
        const float m = fminf(mm[0], mm[1]);

        // Pass 3: tie mask via two independent OR accumulators.
        unsigned a0 = 0, a1 = 0;
        #pragma unroll
        for (int i = 0; i < 8; ++i) {
            a0 |= (d[i]     == m) ? (1u << i)       : 0u;
            a1 |= (d[i + 8] == m) ? (1u << (i + 8)) : 0u;
        }
        const unsigned am = a0 | a1;

        // thr = (m<2) ? m : -1; selection is exactly the tie set when m<2.
        const float cnt = (m < 2.f) ? (float)__popc(am & tmask) : 0.f;

        // dist term: every selected entry has dist == m
        loss = fmaf(m, cnt, loss);

        // Confidence term: (sig-1)^2 if any match else sig^2
        float sig = 1.f / (1.f + __expf(-c4));
        float e   = (cnt > 0.f) ? (sig - 1.f) : sig;
        loss = fmaf(e, e, loss);

        // Class term: (1 - cls_hard)^2 per selected line; cls_hard=1 <=> c5>0
        if (!(c5 > 0.f)) loss += cnt;
    }

    // ---- block reduction (deterministic) ----
    #pragma unroll
    for (int o = 16; o > 0; o >>= 1)
        loss += __shfl_xor_sync(0xffffffffu, loss, o);

    __shared__ float sw[TPB / 32];
    __shared__ bool  s_last;
    const int lane = threadIdx.x & 31;
    const int wid  = threadIdx.x >> 5;
    if (lane == 0) sw[wid] = loss;
    __syncthreads();
    if (wid == 0) {
        float v = (lane < TPB / 32) ? sw[lane] : 0.f;
        #pragma unroll
        for (int o = 2; o > 0; o >>= 1)
            v += __shfl_xor_sync(0xffffffffu, v, o);
        if (lane == 0) {
            g_partials[blockIdx.x] = v;
            __threadfence();
            unsigned t = atomicAdd(&g_ticket, 1u);
            s_last = (t == NBLK - 1);
        }
    }
    __syncthreads();

    // ---- last block folds all partials into the output ----
    if (s_last) {
        __threadfence();  // acquire: make all g_partials visible
        const int t = threadIdx.x;
        float v = 0.f;
        for (int i = t; i < NBLK; i += TPB)   // fixed per-thread order: deterministic
            v += g_partials[i];
        __shared__ float s[TPB];
        s[t] = v;
        __syncthreads();
        #pragma unroll
        for (int o = TPB / 2; o > 0; o >>= 1) {
            if (t < o) s[t] += s[t + o];
            __syncthreads();
        }
        if (t == 0) {
            out[0] = s[0] * (1.0f / BSZ);
            g_ticket = 0;   // reset for the next (graph-replayed) launch
        }
    }
}

extern "C" void kernel_launch(void* const* d_in, const int* in_sizes, int n_in,
                              void* d_out, int out_size)
{
    const float* target = (const float*)d_in[0];
    const float* pred   = (const float*)d_in[1];
    float* out = (float*)d_out;

    yolino_main<<<NBLK, TPB>>>(target, pred, out);
}